// round 6
// baseline (speedup 1.0000x reference)
#include <cuda_runtime.h>
#include <math.h>

// Problem constants
#define NB   2
#define NK   4096
#define NP   16384
#define NKP  (NB*NK)          // 8192 keypoint rows
#define CBEV 256
#define HH   496
#define WW   432
#define HW   (HH*WW)
#define R2   0.64f

// Grid for ball query (cell size = radius = 0.8)
#define GX 87
#define GY 100
#define GZ 5
#define NCELL (GX*GY*GZ)      // 43500
#define CAP 32

#define BEV_BLKS (NKP/8)      // 1024 blocks, 8 rows each
#define SA_BLKS  (NKP/8)      // 1024 blocks, 8 keypoints each
#define NPART 128             // BN partial sets (64 blocks x 2 halves)

// ---- scratch (static device globals; no allocation) ----
__device__ int   g_cellCnt[NB*NCELL];
__device__ int   g_cellPts[NB*NCELL*CAP];
__device__ float g_zs[NKP*128];    // partial z from sa features (k = 0..63)
__device__ float g_zb[NKP*128];    // partial z from bev features (k = 64..319)
__device__ float g_psum[NPART*128];
__device__ float g_psq [NPART*128];
__device__ float g_scale[128];
__device__ float g_shift[128];

__device__ __forceinline__ int cellOf(float x, float lo) {
    return (int)floorf((x - lo) * 1.25f);
}

__global__ void k_init() {
    int i = blockIdx.x*blockDim.x + threadIdx.x;
    if (i < NB*NCELL) g_cellCnt[i] = 0;
}

__global__ void k_bin(const float* __restrict__ pts) {
    int i = blockIdx.x*blockDim.x + threadIdx.x;
    if (i >= NB*NP) return;
    int b = i / NP, p = i % NP;
    float x = pts[i*3+0], y = pts[i*3+1], z = pts[i*3+2];
    int cx = min(max(cellOf(x,   0.0f), 0), GX-1);
    int cy = min(max(cellOf(y, -39.68f),0), GY-1);
    int cz = min(max(cellOf(z,  -3.0f), 0), GZ-1);
    int cell = b*NCELL + (cx*GY + cy)*GZ + cz;
    int slot = atomicAdd(&g_cellCnt[cell], 1);
    if (slot < CAP) g_cellPts[cell*CAP + slot] = p;   // set semantics; order-invariant downstream
}

// Fused producer kernel. Each block finishes its rows' GEMM partial itself, so the
// latency-bound FMA work of early waves hides under later waves' DRAM-bound gathers.
//   blocks [0, BEV_BLKS): 8 rows; bilinear gather (256 ch) -> smem -> partial GEMM k=64..319 -> g_zb
//   blocks [BEV_BLKS, +SA_BLKS): 8 kps; ball query + MLP + maxpool -> smem -> partial GEMM k=0..63 -> g_zs
__global__ void __launch_bounds__(256) k_sabev(
    const float* __restrict__ kps, const float* __restrict__ pts,
    const float* __restrict__ pf,  const float* __restrict__ bev,
    const float* __restrict__ W1, const float* __restrict__ b1,
    const float* __restrict__ W2, const float* __restrict__ b2,
    const float* __restrict__ Wf)
{
    __shared__ float  bfeat[4*512];          // bev features, row-pair f32x2 packed
    __shared__ int4   offs[8];
    __shared__ float4 wts [8];
    __shared__ int    rb  [8];
    __shared__ float  W1s[128], b1s[32], W2s[2048], b2s[64];
    __shared__ int    cidx[8][128];
    __shared__ float  cd2 [8][128];
    __shared__ float  sfeat[4*128];          // sa features, row-pair f32x2 packed

    int t = threadIdx.x;

    if (blockIdx.x < BEV_BLKS) {
        int r0 = blockIdx.x * 8;
        if (t < 8) {
            int row = r0 + t;
            // match reference literally: (kx - 0)/0.16/1.0 ; (ky + 39.68)/0.16/1.0
            float x = kps[row*3+0] / 0.16f;
            float y = (kps[row*3+1] + 39.68f) / 0.16f;
            float fx = floorf(x), fy = floorf(y);
            int x0 = min(max((int)fx,     0), WW-1);
            int x1 = min(max((int)fx + 1, 0), WW-1);
            int y0 = min(max((int)fy,     0), HH-1);
            int y1 = min(max((int)fy + 1, 0), HH-1);
            offs[t] = make_int4(y0*WW + x0, y1*WW + x0, y0*WW + x1, y1*WW + x1);
            wts [t] = make_float4(((float)x1 - x)*((float)y1 - y),
                                  ((float)x1 - x)*(y - (float)y0),
                                  (x - (float)x0)*((float)y1 - y),
                                  (x - (float)x0)*(y - (float)y0));
            rb  [t] = row >> 12;
        }
        __syncthreads();

        int h = t >> 7, c = t & 127;
        // gather: 4 rows x 2 channels per thread = 32 independent LDGs
        #pragma unroll
        for (int i = 0; i < 4; i++) {
            int r = h*4 + i;
            const float* p0 = bev + ((size_t)rb[r]*CBEV + c)*(size_t)HW;
            const float* p1 = p0 + (size_t)128*HW;
            int4  o = offs[r];
            float4 w = wts[r];
            float A0 = __ldg(p0+o.x), B0 = __ldg(p0+o.y), C0 = __ldg(p0+o.z), D0 = __ldg(p0+o.w);
            float A1 = __ldg(p1+o.x), B1 = __ldg(p1+o.y), C1 = __ldg(p1+o.z), D1 = __ldg(p1+o.w);
            bfeat[(r>>1)*512 + 2*c         + (r&1)] = A0*w.x + B0*w.y + C0*w.z + D0*w.w;
            bfeat[(r>>1)*512 + 2*(c + 128) + (r&1)] = A1*w.x + B1*w.y + C1*w.z + D1*w.w;
        }
        __syncthreads();

        // partial GEMM: thread (h,c) -> pairs {2h, 2h+1}, column c, k = 64..319
        unsigned long long acc0 = 0ull, acc1 = 0ull;
        const float* wp = Wf + (size_t)64*128 + c;
        const float* f0 = bfeat + (2*h)*512;
        const float* f1 = f0 + 512;
        #pragma unroll 4
        for (int k = 0; k < 256; k += 2) {
            float w0 = __ldg(wp + (size_t)k*128);
            float w1 = __ldg(wp + (size_t)(k+1)*128);
            unsigned long long w02, w12;
            asm("mov.b64 %0,{%1,%1};" : "=l"(w02) : "f"(w0));
            asm("mov.b64 %0,{%1,%1};" : "=l"(w12) : "f"(w1));
            longlong2 qa = *(const longlong2*)(f0 + 2*k);   // LDS.128 broadcast
            longlong2 qb = *(const longlong2*)(f1 + 2*k);
            asm("fma.rn.f32x2 %0,%1,%2,%0;" : "+l"(acc0) : "l"((unsigned long long)qa.x), "l"(w02));
            asm("fma.rn.f32x2 %0,%1,%2,%0;" : "+l"(acc0) : "l"((unsigned long long)qa.y), "l"(w12));
            asm("fma.rn.f32x2 %0,%1,%2,%0;" : "+l"(acc1) : "l"((unsigned long long)qb.x), "l"(w02));
            asm("fma.rn.f32x2 %0,%1,%2,%0;" : "+l"(acc1) : "l"((unsigned long long)qb.y), "l"(w12));
        }
        float z0, z1, z2, z3;
        asm("mov.b64 {%0,%1},%2;" : "=f"(z0), "=f"(z1) : "l"(acc0));
        asm("mov.b64 {%0,%1},%2;" : "=f"(z2), "=f"(z3) : "l"(acc1));
        int rbase = r0 + 4*h;
        g_zb[(size_t)(rbase+0)*128 + c] = z0;
        g_zb[(size_t)(rbase+1)*128 + c] = z1;
        g_zb[(size_t)(rbase+2)*128 + c] = z2;
        g_zb[(size_t)(rbase+3)*128 + c] = z3;
        return;
    }

    // ---- SA: one warp per keypoint, 8 warps per block ----
    if (t < 128) W1s[t] = W1[t];
    for (int i = t; i < 2048; i += 256) W2s[i] = W2[i];
    if (t < 32) b1s[t] = b1[t];
    if (t < 64) b2s[t] = b2[t];
    __syncthreads();

    int warp = t >> 5, lane = t & 31;
    int r0s = (blockIdx.x - BEV_BLKS)*8;
    int kpi = r0s + warp;                // 0..8191
    int b = kpi >> 12;
    float kx = kps[kpi*3+0], ky = kps[kpi*3+1], kz = kps[kpi*3+2];
    int cx = min(max(cellOf(kx,   0.0f), 0), GX-1);
    int cy = min(max(cellOf(ky, -39.68f),0), GY-1);
    int cz = min(max(cellOf(kz,  -3.0f), 0), GZ-1);

    const float* ptsb = pts + (size_t)b*NP*3;

    int n_l = 0;
    const int* cp_l = g_cellPts;
    if (lane < 27) {
        int ccx = cx + lane/9 - 1;
        int ccy = cy + (lane/3)%3 - 1;
        int ccz = cz + lane%3 - 1;
        if (ccx >= 0 && ccx < GX && ccy >= 0 && ccy < GY && ccz >= 0 && ccz < GZ) {
            int cell = b*NCELL + (ccx*GY + ccy)*GZ + ccz;
            n_l = min(g_cellCnt[cell], CAP);
            cp_l = &g_cellPts[cell*CAP];
        }
    }
    int maxn = n_l;
    #pragma unroll
    for (int o = 16; o; o >>= 1) maxn = max(maxn, __shfl_xor_sync(0xffffffffu, maxn, o));

    int cnt = 0;
    for (int s = 0; s < maxn; s++) {
        bool act = s < n_l;
        int pi = act ? cp_l[s] : 0;
        float d2 = 1e30f;
        if (act) {
            float ddx = ptsb[pi*3+0]-kx;
            float ddy = ptsb[pi*3+1]-ky;
            float ddz = ptsb[pi*3+2]-kz;
            d2 = ddx*ddx + ddy*ddy + ddz*ddz;
        }
        bool val = act && (d2 < R2);
        unsigned m = __ballot_sync(0xffffffffu, val);
        int pos = cnt + __popc(m & ((1u<<lane)-1u));
        if (val && pos < 128) { cidx[warp][pos] = pi; cd2[warp][pos] = d2; }
        cnt += __popc(m);
    }
    if (cnt > 128) cnt = 128;
    __syncwarp();
    if (cnt > 32) {   // ultra-rare: keep 32 smallest d2 (same set as top_k; order irrelevant for maxpool)
        if (lane == 0) {
            for (int i = 32; i < cnt; i++) {
                float d = cd2[warp][i];
                int mi = 0; float mv = cd2[warp][0];
                for (int j = 1; j < 32; j++) { float v = cd2[warp][j]; if (v > mv) { mv = v; mi = j; } }
                if (d < mv) { cd2[warp][mi] = d; cidx[warp][mi] = cidx[warp][i]; }
            }
        }
        __syncwarp();
        cnt = 32;
    }

    float w10 = W1s[lane], w11 = W1s[32+lane], w12 = W1s[64+lane], w13 = W1s[96+lane];
    float b1v = b1s[lane];
    float a0 = 0.f, a1 = 0.f;   // relu >= 0 so 0-init == reference no-valid case
    const float* pfb = pf + (size_t)b*NP;
    for (int nIt = 0; nIt < cnt; nIt++) {
        int pi = cidx[warp][nIt];
        float dx = ptsb[pi*3+0]-kx;
        float dy = ptsb[pi*3+1]-ky;
        float dz = ptsb[pi*3+2]-kz;
        float f  = pfb[pi];
        float hv = fmaxf(fmaf(dx,w10, fmaf(dy,w11, fmaf(dz,w12, fmaf(f,w13, b1v)))), 0.f);
        float t0 = b2s[lane], t1 = b2s[32+lane];
        #pragma unroll
        for (int j = 0; j < 32; j++) {
            float hj = __shfl_sync(0xffffffffu, hv, j);
            t0 = fmaf(hj, W2s[j*64+lane],    t0);
            t1 = fmaf(hj, W2s[j*64+32+lane], t1);
        }
        a0 = fmaxf(a0, fmaxf(t0, 0.f));
        a1 = fmaxf(a1, fmaxf(t1, 0.f));
    }
    // stash features row-pair f32x2 packed: k index = lane (a0) and 32+lane (a1)
    sfeat[(warp>>1)*128 + 2*lane        + (warp&1)] = a0;
    sfeat[(warp>>1)*128 + 2*(32 + lane) + (warp&1)] = a1;
    __syncthreads();

    // partial GEMM: thread (h,c) -> pairs {2h, 2h+1}, column c, k = 0..63
    {
        int h = t >> 7, c = t & 127;
        unsigned long long acc0 = 0ull, acc1 = 0ull;
        const float* wp = Wf + c;
        const float* f0 = sfeat + (2*h)*128;
        const float* f1 = f0 + 128;
        #pragma unroll 4
        for (int k = 0; k < 64; k += 2) {
            float w0 = __ldg(wp + (size_t)k*128);
            float w1 = __ldg(wp + (size_t)(k+1)*128);
            unsigned long long w02, w12;
            asm("mov.b64 %0,{%1,%1};" : "=l"(w02) : "f"(w0));
            asm("mov.b64 %0,{%1,%1};" : "=l"(w12) : "f"(w1));
            longlong2 qa = *(const longlong2*)(f0 + 2*k);
            longlong2 qb = *(const longlong2*)(f1 + 2*k);
            asm("fma.rn.f32x2 %0,%1,%2,%0;" : "+l"(acc0) : "l"((unsigned long long)qa.x), "l"(w02));
            asm("fma.rn.f32x2 %0,%1,%2,%0;" : "+l"(acc0) : "l"((unsigned long long)qa.y), "l"(w12));
            asm("fma.rn.f32x2 %0,%1,%2,%0;" : "+l"(acc1) : "l"((unsigned long long)qb.x), "l"(w02));
            asm("fma.rn.f32x2 %0,%1,%2,%0;" : "+l"(acc1) : "l"((unsigned long long)qb.y), "l"(w12));
        }
        float z0, z1, z2, z3;
        asm("mov.b64 {%0,%1},%2;" : "=f"(z0), "=f"(z1) : "l"(acc0));
        asm("mov.b64 {%0,%1},%2;" : "=f"(z2), "=f"(z3) : "l"(acc1));
        int rbase = r0s + 4*h;
        g_zs[(size_t)(rbase+0)*128 + c] = z0;
        g_zs[(size_t)(rbase+1)*128 + c] = z1;
        g_zs[(size_t)(rbase+2)*128 + c] = z2;
        g_zs[(size_t)(rbase+3)*128 + c] = z3;
    }
}

// BN partials from z = zs + zb: 64 blocks x 256 threads; (block, half) owns 64 rows.
__global__ void __launch_bounds__(256) k_part() {
    int h = threadIdx.x >> 7, c = threadIdx.x & 127;
    int row0 = blockIdx.x*128 + h*64;
    float s = 0.f, q = 0.f;
    #pragma unroll 4
    for (int r = 0; r < 64; r++) {
        size_t i = (size_t)(row0 + r)*128 + c;
        float z = g_zs[i] + g_zb[i];
        s += z; q += z*z;
    }
    g_psum[(blockIdx.x*2 + h)*128 + c] = s;
    g_psq [(blockIdx.x*2 + h)*128 + c] = q;
}

// One block per channel; tree-reduce 128 partials. Deterministic.
__global__ void __launch_bounds__(128) k_stats(
    const float* __restrict__ gamma, const float* __restrict__ beta)
{
    __shared__ float sh_s[128], sh_q[128];
    int c = blockIdx.x, t = threadIdx.x;
    sh_s[t] = g_psum[t*128 + c];
    sh_q[t] = g_psq [t*128 + c];
    __syncthreads();
    #pragma unroll
    for (int o = 64; o; o >>= 1) {
        if (t < o) { sh_s[t] += sh_s[t+o]; sh_q[t] += sh_q[t+o]; }
        __syncthreads();
    }
    if (t == 0) {
        float inv = 1.0f / (float)NKP;
        float mu  = sh_s[0] * inv;
        float var = sh_q[0] * inv - mu*mu;
        float sc  = rsqrtf(var + 1e-5f) * gamma[c];
        g_scale[c] = sc;
        g_shift[c] = beta[c] - mu * sc;
    }
}

__global__ void k_norm(float* __restrict__ out) {
    int i = blockIdx.x*blockDim.x + threadIdx.x;
    int c = i & 127;
    float z = g_zs[i] + g_zb[i];
    out[i] = fmaxf(fmaf(z, g_scale[c], g_shift[c]), 0.f);
}

extern "C" void kernel_launch(void* const* d_in, const int* /*in_sizes*/, int /*n_in*/,
                              void* d_out, int /*out_size*/) {
    const float* kps = (const float*)d_in[0];
    const float* pts = (const float*)d_in[1];
    const float* pf  = (const float*)d_in[2];
    const float* bev = (const float*)d_in[3];
    const float* W1  = (const float*)d_in[4];
    const float* b1  = (const float*)d_in[5];
    const float* W2  = (const float*)d_in[6];
    const float* b2  = (const float*)d_in[7];
    const float* Wf  = (const float*)d_in[8];
    const float* gm  = (const float*)d_in[9];
    const float* bt  = (const float*)d_in[10];

    k_init <<<(NB*NCELL + 255)/256, 256>>>();
    k_bin  <<<(NB*NP    + 255)/256, 256>>>(pts);
    k_sabev<<<BEV_BLKS + SA_BLKS, 256>>>(kps, pts, pf, bev, W1, b1, W2, b2, Wf);
    k_part <<<64, 256>>>();
    k_stats<<<128, 128>>>(gm, bt);
    k_norm <<<(NKP*128)/256, 256>>>((float*)d_out);
}

// round 7
// speedup vs baseline: 1.8075x; 1.8075x over previous
#include <cuda_runtime.h>
#include <math.h>

// Problem constants
#define NB   2
#define NK   4096
#define NP   16384
#define NKP  (NB*NK)          // 8192 keypoint rows
#define CBEV 256
#define HH   496
#define WW   432
#define HW   (HH*WW)
#define R2   0.64f

// Grid for ball query (cell size = radius = 0.8)
#define GX 87
#define GY 100
#define GZ 5
#define NCELL (GX*GY*GZ)      // 43500
#define CAP 32

#define BEV_BLKS (NKP/4)      // 2048 bev blocks, 4 rows each
#define SA_BLKS  (NKP/8)      // 1024 sa blocks, 8 keypoints each

// GEMM: 16 rows per tile, K split in 2 halves of 160 -> 1024 blocks x 256 threads
#define ROWS 16
#define PAIRS (ROWS/2)
#define KSPLIT 160
#define GTILES (NKP/ROWS)     // 512 row tiles
#define NPART (GTILES*2)      // 1024 BN partial sets

// ---- scratch (static device globals; no allocation) ----
__device__ int   g_cellCnt[NB*NCELL];
__device__ int   g_cellPts[NB*NCELL*CAP];
__device__ float g_sa[NKP*64];
__device__ float g_pbev[NKP*CBEV];
__device__ float g_zp0[NKP*128];   // z partial, k in [0,160)
__device__ float g_zp1[NKP*128];   // z partial, k in [160,320)
__device__ float g_psum[NPART*128];
__device__ float g_psq [NPART*128];
__device__ float g_scale[128];
__device__ float g_shift[128];

__device__ __forceinline__ int cellOf(float x, float lo) {
    return (int)floorf((x - lo) * 1.25f);
}

__global__ void k_init() {
    int i = blockIdx.x*blockDim.x + threadIdx.x;
    if (i < NB*NCELL) g_cellCnt[i] = 0;
}

__global__ void k_bin(const float* __restrict__ pts) {
    int i = blockIdx.x*blockDim.x + threadIdx.x;
    if (i >= NB*NP) return;
    int b = i / NP, p = i % NP;
    float x = pts[i*3+0], y = pts[i*3+1], z = pts[i*3+2];
    int cx = min(max(cellOf(x,   0.0f), 0), GX-1);
    int cy = min(max(cellOf(y, -39.68f),0), GY-1);
    int cz = min(max(cellOf(z,  -3.0f), 0), GZ-1);
    int cell = b*NCELL + (cx*GY + cy)*GZ + cz;
    int slot = atomicAdd(&g_cellCnt[cell], 1);
    if (slot < CAP) g_cellPts[cell*CAP + slot] = p;   // set semantics; order-invariant downstream
}

// Fused: round-robin 2 bev blocks : 1 sa block so latency-bound sa warps stay
// co-resident with DRAM-bound bev warps for the whole kernel (no pure-sa tail).
__global__ void __launch_bounds__(256) k_sabev(
    const float* __restrict__ kps, const float* __restrict__ pts,
    const float* __restrict__ pf,  const float* __restrict__ bev,
    const float* __restrict__ W1, const float* __restrict__ b1,
    const float* __restrict__ W2, const float* __restrict__ b2)
{
    int t = threadIdx.x;
    int m = blockIdx.x % 3;           // 0,1 -> bev ; 2 -> sa
    int g = blockIdx.x / 3;

    if (m < 2) {
        // ---- BEV gather: 4 rows per block; thread: 2 rows x 2 channels = 16 LDGs ----
        int bi   = 2*g + m;           // 0..2047
        int c    = t & 127;
        int row0 = bi*4 + (t >> 7)*2;
        #pragma unroll
        for (int rr = 0; rr < 2; rr++) {
            int row = row0 + rr;
            int b = row >> 12;
            // match reference literally: (kx - 0)/0.16/1.0 ; (ky + 39.68)/0.16/1.0
            float x = kps[row*3+0] / 0.16f;
            float y = (kps[row*3+1] + 39.68f) / 0.16f;
            float fx = floorf(x), fy = floorf(y);
            int x0 = min(max((int)fx,     0), WW-1);
            int x1 = min(max((int)fx + 1, 0), WW-1);
            int y0 = min(max((int)fy,     0), HH-1);
            int y1 = min(max((int)fy + 1, 0), HH-1);
            float wa = ((float)x1 - x)*((float)y1 - y);
            float wb = ((float)x1 - x)*(y - (float)y0);
            float wc = (x - (float)x0)*((float)y1 - y);
            float wd = (x - (float)x0)*(y - (float)y0);
            const float* p0 = bev + ((size_t)b*CBEV + c)*(size_t)HW;
            const float* p1 = p0 + (size_t)128*HW;
            int oa = y0*WW + x0, ob = y1*WW + x0, oc = y0*WW + x1, od = y1*WW + x1;
            float A0 = __ldg(p0+oa), B0 = __ldg(p0+ob), C0 = __ldg(p0+oc), D0 = __ldg(p0+od);
            float A1 = __ldg(p1+oa), B1 = __ldg(p1+ob), C1 = __ldg(p1+oc), D1 = __ldg(p1+od);
            g_pbev[(size_t)row*CBEV + c]       = A0*wa + B0*wb + C0*wc + D0*wd;
            g_pbev[(size_t)row*CBEV + c + 128] = A1*wa + B1*wb + C1*wc + D1*wd;
        }
        return;
    }

    // ---- SA: one warp per keypoint, 8 warps per block ----
    __shared__ float W1s[128], b1s[32], W2s[2048], b2s[64];
    __shared__ int   cidx[8][128];
    __shared__ float cd2 [8][128];
    if (t < 128) W1s[t] = W1[t];
    for (int i = t; i < 2048; i += 256) W2s[i] = W2[i];
    if (t < 32) b1s[t] = b1[t];
    if (t < 64) b2s[t] = b2[t];
    __syncthreads();

    int warp = t >> 5, lane = t & 31;
    int kpi = g*8 + warp;             // 0..8191
    int b = kpi >> 12;
    float kx = kps[kpi*3+0], ky = kps[kpi*3+1], kz = kps[kpi*3+2];
    int cx = min(max(cellOf(kx,   0.0f), 0), GX-1);
    int cy = min(max(cellOf(ky, -39.68f),0), GY-1);
    int cz = min(max(cellOf(kz,  -3.0f), 0), GZ-1);

    const float* ptsb = pts + (size_t)b*NP*3;

    int n_l = 0;
    const int* cp_l = g_cellPts;
    if (lane < 27) {
        int ccx = cx + lane/9 - 1;
        int ccy = cy + (lane/3)%3 - 1;
        int ccz = cz + lane%3 - 1;
        if (ccx >= 0 && ccx < GX && ccy >= 0 && ccy < GY && ccz >= 0 && ccz < GZ) {
            int cell = b*NCELL + (ccx*GY + ccy)*GZ + ccz;
            n_l = min(g_cellCnt[cell], CAP);
            cp_l = &g_cellPts[cell*CAP];
        }
    }
    int maxn = n_l;
    #pragma unroll
    for (int o = 16; o; o >>= 1) maxn = max(maxn, __shfl_xor_sync(0xffffffffu, maxn, o));

    int cnt = 0;
    for (int s = 0; s < maxn; s++) {
        bool act = s < n_l;
        int pi = act ? cp_l[s] : 0;
        float d2 = 1e30f;
        if (act) {
            float ddx = ptsb[pi*3+0]-kx;
            float ddy = ptsb[pi*3+1]-ky;
            float ddz = ptsb[pi*3+2]-kz;
            d2 = ddx*ddx + ddy*ddy + ddz*ddz;
        }
        bool val = act && (d2 < R2);
        unsigned mm = __ballot_sync(0xffffffffu, val);
        int pos = cnt + __popc(mm & ((1u<<lane)-1u));
        if (val && pos < 128) { cidx[warp][pos] = pi; cd2[warp][pos] = d2; }
        cnt += __popc(mm);
    }
    if (cnt > 128) cnt = 128;
    __syncwarp();
    if (cnt > 32) {   // ultra-rare: keep 32 smallest d2 (same set as top_k; order irrelevant for maxpool)
        if (lane == 0) {
            for (int i = 32; i < cnt; i++) {
                float d = cd2[warp][i];
                int mi = 0; float mv = cd2[warp][0];
                for (int j = 1; j < 32; j++) { float v = cd2[warp][j]; if (v > mv) { mv = v; mi = j; } }
                if (d < mv) { cd2[warp][mi] = d; cidx[warp][mi] = cidx[warp][i]; }
            }
        }
        __syncwarp();
        cnt = 32;
    }

    float w10 = W1s[lane], w11 = W1s[32+lane], w12 = W1s[64+lane], w13 = W1s[96+lane];
    float b1v = b1s[lane];
    float a0 = 0.f, a1 = 0.f;   // relu >= 0 so 0-init == reference no-valid case
    const float* pfb = pf + (size_t)b*NP;
    for (int nIt = 0; nIt < cnt; nIt++) {
        int pi = cidx[warp][nIt];
        float dx = ptsb[pi*3+0]-kx;
        float dy = ptsb[pi*3+1]-ky;
        float dz = ptsb[pi*3+2]-kz;
        float f  = pfb[pi];
        float hv = fmaxf(fmaf(dx,w10, fmaf(dy,w11, fmaf(dz,w12, fmaf(f,w13, b1v)))), 0.f);
        float t0 = b2s[lane], t1 = b2s[32+lane];
        #pragma unroll
        for (int j = 0; j < 32; j++) {
            float hj = __shfl_sync(0xffffffffu, hv, j);
            t0 = fmaf(hj, W2s[j*64+lane],    t0);
            t1 = fmaf(hj, W2s[j*64+32+lane], t1);
        }
        a0 = fmaxf(a0, fmaxf(t0, 0.f));
        a1 = fmaxf(a1, fmaxf(t1, 0.f));
    }
    g_sa[kpi*64 + lane]      = a0;
    g_sa[kpi*64 + 32 + lane] = a1;
}

// GEMM with K-split: block g -> row tile g>>1 (16 rows), k-half g&1 (160 k-values).
// 1024 blocks x 256 threads -> ~full occupancy. fma.rn.f32x2 == 2x scalar fma.rn.
__global__ void __launch_bounds__(256) k_gemm(const float* __restrict__ Wf)
{
    __shared__ float fsp[PAIRS*320];   // pair p: element (kk,parity) at [p*320 + 2kk + parity]
    int t = threadIdx.x;
    int tile = blockIdx.x >> 1, kh = blockIdx.x & 1;
    int r0 = tile * ROWS;
    int k0 = kh * KSPLIT;

    for (int i = t; i < ROWS*KSPLIT; i += 256) {
        int r = i / KSPLIT, kk = i - r*KSPLIT;
        int k = k0 + kk;
        float v = (k < 64) ? g_sa[(size_t)(r0+r)*64 + k]
                           : g_pbev[(size_t)(r0+r)*CBEV + (k-64)];
        fsp[(r>>1)*320 + 2*kk + (r&1)] = v;
    }
    __syncthreads();

    int h = t >> 7, c = t & 127;
    unsigned long long acc[4];
    #pragma unroll
    for (int j = 0; j < 4; j++) acc[j] = 0ull;

    const float* wcol = Wf + (size_t)k0*128 + c;
    const float* base = fsp + (h*4)*320;
    for (int kk = 0; kk < KSPLIT; kk += 2) {
        float wa = wcol[(size_t)kk*128];
        float wb = wcol[(size_t)(kk+1)*128];
        unsigned long long w2a, w2b;
        asm("mov.b64 %0,{%1,%1};" : "=l"(w2a) : "f"(wa));
        asm("mov.b64 %0,{%1,%1};" : "=l"(w2b) : "f"(wb));
        #pragma unroll
        for (int j = 0; j < 4; j++) {
            longlong2 q = *(const longlong2*)(base + j*320 + 2*kk);   // LDS.128 broadcast
            asm("fma.rn.f32x2 %0,%1,%2,%0;" : "+l"(acc[j]) : "l"((unsigned long long)q.x), "l"(w2a));
            asm("fma.rn.f32x2 %0,%1,%2,%0;" : "+l"(acc[j]) : "l"((unsigned long long)q.y), "l"(w2b));
        }
    }

    float* zp = kh ? g_zp1 : g_zp0;
    #pragma unroll
    for (int j = 0; j < 4; j++) {
        float zlo, zhi;
        asm("mov.b64 {%0,%1},%2;" : "=f"(zlo), "=f"(zhi) : "l"(acc[j]));
        int p = h*4 + j;
        zp[(size_t)(r0 + 2*p    )*128 + c] = zlo;
        zp[(size_t)(r0 + 2*p + 1)*128 + c] = zhi;
    }
}

// BN partials from z = zp0 + zp1: 512 blocks x 256 threads; (block, half) owns 8 rows.
__global__ void __launch_bounds__(256) k_part() {
    int h = threadIdx.x >> 7, c = threadIdx.x & 127;
    int row0 = blockIdx.x*16 + h*8;
    float s = 0.f, q = 0.f;
    #pragma unroll
    for (int r = 0; r < 8; r++) {
        size_t i = (size_t)(row0 + r)*128 + c;
        float z = g_zp0[i] + g_zp1[i];
        s += z; q += z*z;
    }
    g_psum[(blockIdx.x*2 + h)*128 + c] = s;
    g_psq [(blockIdx.x*2 + h)*128 + c] = q;
}

// One block per channel; 256 threads reduce 1024 partials. Deterministic.
__global__ void __launch_bounds__(256) k_stats(
    const float* __restrict__ gamma, const float* __restrict__ beta)
{
    __shared__ float sh_s[256], sh_q[256];
    int c = blockIdx.x, t = threadIdx.x;
    float s = 0.f, q = 0.f;
    #pragma unroll
    for (int i = t; i < NPART; i += 256) { s += g_psum[i*128+c]; q += g_psq[i*128+c]; }
    sh_s[t] = s; sh_q[t] = q;
    __syncthreads();
    #pragma unroll
    for (int o = 128; o; o >>= 1) {
        if (t < o) { sh_s[t] += sh_s[t+o]; sh_q[t] += sh_q[t+o]; }
        __syncthreads();
    }
    if (t == 0) {
        float inv = 1.0f / (float)NKP;
        float mu  = sh_s[0] * inv;
        float var = sh_q[0] * inv - mu*mu;
        float sc  = rsqrtf(var + 1e-5f) * gamma[c];
        g_scale[c] = sc;
        g_shift[c] = beta[c] - mu * sc;
    }
}

__global__ void k_norm(float* __restrict__ out) {
    int i = blockIdx.x*blockDim.x + threadIdx.x;
    int c = i & 127;
    float z = g_zp0[i] + g_zp1[i];
    out[i] = fmaxf(fmaf(z, g_scale[c], g_shift[c]), 0.f);
}

extern "C" void kernel_launch(void* const* d_in, const int* /*in_sizes*/, int /*n_in*/,
                              void* d_out, int /*out_size*/) {
    const float* kps = (const float*)d_in[0];
    const float* pts = (const float*)d_in[1];
    const float* pf  = (const float*)d_in[2];
    const float* bev = (const float*)d_in[3];
    const float* W1  = (const float*)d_in[4];
    const float* b1  = (const float*)d_in[5];
    const float* W2  = (const float*)d_in[6];
    const float* b2  = (const float*)d_in[7];
    const float* Wf  = (const float*)d_in[8];
    const float* gm  = (const float*)d_in[9];
    const float* bt  = (const float*)d_in[10];

    k_init <<<(NB*NCELL + 255)/256, 256>>>();
    k_bin  <<<(NB*NP    + 255)/256, 256>>>(pts);
    k_sabev<<<BEV_BLKS + SA_BLKS, 256>>>(kps, pts, pf, bev, W1, b1, W2, b2);
    k_gemm <<<GTILES*2, 256>>>(Wf);
    k_part <<<GTILES, 256>>>();
    k_stats<<<128, 256>>>(gm, bt);
    k_norm <<<(NKP*128)/256, 256>>>((float*)d_out);
}